// round 2
// baseline (speedup 1.0000x reference)
#include <cuda_runtime.h>
#include <cstdint>
#include <math.h>

#define FULL_MASK 0xFFFFFFFFu

constexpr int   N_COLS = 32768;
constexpr int   TPB    = 512;
constexpr int   F4PT   = N_COLS / 4 / TPB;   // 16 float4 per thread per pass
constexpr int   KTOP   = 64;
constexpr int   CAP    = 1024;               // candidate buffer capacity
constexpr float THRESH = 2.45f;              // E[count >= THRESH] ~ 234 for N(0,1)
constexpr int   GRID   = 296;                // 2 persistent CTAs per SM (148 SMs)
constexpr int   NWARP  = TPB / 32;           // 16

// Order-preserving float->uint key (larger float => larger key)
__device__ __forceinline__ unsigned f2k(float f) {
    unsigned u = __float_as_uint(f);
    return (u & 0x80000000u) ? ~u : (u | 0x80000000u);
}
__device__ __forceinline__ float k2f(unsigned k) {
    unsigned u = (k & 0x80000000u) ? (k & 0x7FFFFFFFu) : ~k;
    return __uint_as_float(u);
}

__global__ __launch_bounds__(TPB, 2)
void remaxkv_kernel(const float* __restrict__ x, float* __restrict__ out, int rows) {
    const int tid  = threadIdx.x;
    const int lane = tid & 31;
    const int warp = tid >> 5;

    __shared__ float    s_cand[CAP];
    __shared__ float    s_msum[NWARP];
    __shared__ double   s_dsum[NWARP];
    __shared__ int      s_cnt[NWARP];
    __shared__ int      s_ncand;
    __shared__ int      s_fb;
    __shared__ int      s_tot;
    __shared__ float    s_mag;
    __shared__ float    s_ratio;

    for (int row = blockIdx.x; row < rows; row += gridDim.x) {
        const float4* xr   = reinterpret_cast<const float4*>(x   + (size_t)row * N_COLS);
        float4*       outr = reinterpret_cast<float4*>      (out + (size_t)row * N_COLS);

        if (tid == 0) s_ncand = 0;
        __syncthreads();   // also guarantees previous row fully retired before smem reuse

        // ================= Pass 1: stream row, relu-sum + candidate compaction ====
        float ms = 0.f;
#pragma unroll
        for (int ii = 0; ii < F4PT; ii += 8) {
            float4 t[8];
#pragma unroll
            for (int u = 0; u < 8; u++) t[u] = __ldcg(xr + (ii + u) * TPB + tid);
#pragma unroll
            for (int u = 0; u < 8; u++) {
                float4 v = t[u];
                ms += fmaxf(v.x, 0.f) + fmaxf(v.y, 0.f) + fmaxf(v.z, 0.f) + fmaxf(v.w, 0.f);
                float m4 = fmaxf(fmaxf(v.x, v.y), fmaxf(v.z, v.w));
                if (m4 >= THRESH) {          // rare (~2.8% of float4s)
                    if (v.x >= THRESH) { int s = atomicAdd(&s_ncand, 1); if (s < CAP) s_cand[s] = v.x; }
                    if (v.y >= THRESH) { int s = atomicAdd(&s_ncand, 1); if (s < CAP) s_cand[s] = v.y; }
                    if (v.z >= THRESH) { int s = atomicAdd(&s_ncand, 1); if (s < CAP) s_cand[s] = v.z; }
                    if (v.w >= THRESH) { int s = atomicAdd(&s_ncand, 1); if (s < CAP) s_cand[s] = v.w; }
                }
            }
        }
        // deterministic warp reduce of relu-sum
#pragma unroll
        for (int o = 16; o; o >>= 1) ms += __shfl_xor_sync(FULL_MASK, ms, o);
        if (lane == 0) s_msum[warp] = ms;
        __syncthreads();

        // ================= Select: single warp, exact K-th via key bisection ======
        if (warp == 0) {
            float m = (lane < NWARP) ? s_msum[lane] : 0.f;
#pragma unroll
            for (int o = 16; o; o >>= 1) m += __shfl_xor_sync(FULL_MASK, m, o);

            int nc = s_ncand;
            bool fb = (nc < KTOP) || (nc > CAP);
            if (!fb) {
                unsigned lo = f2k(THRESH);          // count(>=lo) = nc >= K
                unsigned hi = 0xFF800000u;          // key(+inf): count(>=hi) = 0 < K
                while (hi - lo > 1u) {
                    unsigned mid = lo + ((hi - lo) >> 1);
                    int c = 0;
                    for (int j = lane; j < nc; j += 32) c += (f2k(s_cand[j]) >= mid) ? 1 : 0;
                    c = __reduce_add_sync(FULL_MASK, c);
                    if (c >= KTOP) lo = mid; else hi = mid;
                }
                // exact top-K sum, order-independent (int64 fixed point => deterministic)
                long long acc = 0; int cg = 0;
                for (int j = lane; j < nc; j += 32) {
                    float v = s_cand[j];
                    if (f2k(v) > lo) { acc += (long long)((double)v * 4294967296.0); cg++; }
                }
#pragma unroll
                for (int o = 16; o; o >>= 1) acc += __shfl_xor_sync(FULL_MASK, acc, o);
                cg = __reduce_add_sync(FULL_MASK, cg);
                if (lane == 0) {
                    double magk = (double)acc * (1.0 / 4294967296.0)
                                + (double)(KTOP - cg) * (double)k2f(lo);
                    float r = (float)(magk / (double)m);
                    if (!isfinite(r)) r = 0.f;
                    s_ratio = r;
                    s_fb = 0;
                }
            } else if (lane == 0) {
                s_fb = 1;
                s_mag = m;
            }
        }
        __syncthreads();

        // ================= Generic fallback (statistically unreachable here) ======
        if (s_fb) {
            unsigned lo = 0u, hi = 0xFFFFFFFFu;
            while (hi - lo > 1u) {
                unsigned mid = lo + ((hi - lo) >> 1);
                int c = 0;
                for (int i = tid; i < N_COLS / 4; i += TPB) {
                    float4 v = __ldcg(xr + i);
                    c += (f2k(v.x) >= mid) + (f2k(v.y) >= mid) + (f2k(v.z) >= mid) + (f2k(v.w) >= mid);
                }
                c = __reduce_add_sync(FULL_MASK, c);
                if (lane == 0) s_cnt[warp] = c;
                __syncthreads();
                if (warp == 0) {
                    int cc = (lane < NWARP) ? s_cnt[lane] : 0;
                    cc = __reduce_add_sync(FULL_MASK, cc);
                    if (lane == 0) s_tot = cc;
                }
                __syncthreads();
                if (s_tot >= KTOP) lo = mid; else hi = mid;
                __syncthreads();
            }
            double s = 0.0; int cg = 0;
            for (int i = tid; i < N_COLS / 4; i += TPB) {
                float4 v = __ldcg(xr + i);
                if (f2k(v.x) > lo) { s += v.x; cg++; }
                if (f2k(v.y) > lo) { s += v.y; cg++; }
                if (f2k(v.z) > lo) { s += v.z; cg++; }
                if (f2k(v.w) > lo) { s += v.w; cg++; }
            }
#pragma unroll
            for (int o = 16; o; o >>= 1) s += __shfl_xor_sync(FULL_MASK, s, o);
            cg = __reduce_add_sync(FULL_MASK, cg);
            if (lane == 0) { s_dsum[warp] = s; s_cnt[warp] = cg; }
            __syncthreads();
            if (warp == 0) {
                double ss = (lane < NWARP) ? s_dsum[lane] : 0.0;
#pragma unroll
                for (int o = 16; o; o >>= 1) ss += __shfl_xor_sync(FULL_MASK, ss, o);
                int cc = (lane < NWARP) ? s_cnt[lane] : 0;
                cc = __reduce_add_sync(FULL_MASK, cc);
                if (lane == 0) {
                    double magk = ss + (double)(KTOP - cc) * (double)k2f(lo);
                    float r = (float)(magk / (double)s_mag);
                    if (!isfinite(r)) r = 0.f;
                    s_ratio = r;
                }
            }
            __syncthreads();
        }

        // ================= Pass 2: L2 re-read, scale, streaming store =============
        float r = s_ratio;
#pragma unroll
        for (int ii = 0; ii < F4PT; ii += 8) {
            float4 t[8];
#pragma unroll
            for (int u = 0; u < 8; u++) t[u] = __ldcs(xr + (ii + u) * TPB + tid);
#pragma unroll
            for (int u = 0; u < 8; u++) {
                float4 v = t[u], o;
                o.x = fmaxf(v.x, 0.f) * r;
                o.y = fmaxf(v.y, 0.f) * r;
                o.z = fmaxf(v.z, 0.f) * r;
                o.w = fmaxf(v.w, 0.f) * r;
                __stcs(outr + (ii + u) * TPB + tid, o);
            }
        }
    }
}

extern "C" void kernel_launch(void* const* d_in, const int* in_sizes, int n_in,
                              void* d_out, int out_size) {
    const float* x  = (const float*)d_in[0];
    float*      out = (float*)d_out;
    int n    = in_sizes[0];
    int rows = n / N_COLS;
    int grid = rows < GRID ? rows : GRID;
    remaxkv_kernel<<<grid, TPB>>>(x, out, rows);
}

// round 3
// speedup vs baseline: 2.5571x; 2.5571x over previous
#include <cuda_runtime.h>
#include <cstdint>
#include <math.h>

#define FULL_MASK 0xFFFFFFFFu

constexpr int   N_COLS = 32768;
constexpr int   TPB    = 512;
constexpr int   F4PT   = N_COLS / 4 / TPB;   // 16 float4 per thread
constexpr int   KTOP   = 64;
constexpr int   NWARP  = TPB / 32;           // 16
constexpr int   WCAP   = 64;                 // per-warp candidate slots (mean ~14.6, 13 sigma margin)
constexpr int   CAP    = NWARP * WCAP;       // 1024
constexpr float THRESH = 2.45f;              // E[count >= T] ~ 234 per row of N(0,1)

// Order-preserving float->uint key (larger float => larger key)
__device__ __forceinline__ unsigned f2k(float f) {
    unsigned u = __float_as_uint(f);
    return (u & 0x80000000u) ? ~u : (u | 0x80000000u);
}
__device__ __forceinline__ float k2f(unsigned k) {
    unsigned u = (k & 0x80000000u) ? (k & 0x7FFFFFFFu) : ~k;
    return __uint_as_float(u);
}

__global__ __launch_bounds__(TPB, 2)
void remaxkv_kernel(const float* __restrict__ x, float* __restrict__ out) {
    const int row  = blockIdx.x;
    const int tid  = threadIdx.x;
    const int lane = tid & 31;
    const int warp = tid >> 5;

    const float4* xr   = reinterpret_cast<const float4*>(x   + (size_t)row * N_COLS);
    float4*       outr = reinterpret_cast<float4*>      (out + (size_t)row * N_COLS);

    __shared__ unsigned  s_wkey[NWARP][WCAP];
    __shared__ unsigned  s_key[CAP];
    __shared__ int       s_wcnt[NWARP];
    __shared__ int       s_off[NWARP];
    __shared__ float     s_msum[NWARP];
    __shared__ long long s_acc[NWARP];
    __shared__ int       s_cnt[NWARP];
    __shared__ double    s_dsum[NWARP];
    __shared__ int       s_nc, s_fb, s_tot;
    __shared__ unsigned  s_kth;
    __shared__ float     s_mag, s_ratio;

    // ============ Pass 1: stream row; relu-sum + atomic-free warp compaction ====
    float ms = 0.f;
    int   wcnt = 0;          // warp-uniform candidate count (ballot-derived)
    bool  ovf  = false;
#pragma unroll
    for (int ii = 0; ii < F4PT; ii += 8) {
        float4 t[8];
#pragma unroll
        for (int u = 0; u < 8; u++) t[u] = __ldcg(xr + (ii + u) * TPB + tid);
#pragma unroll
        for (int u = 0; u < 8; u++) {
            float4 v = t[u];
            ms += fmaxf(v.x, 0.f) + fmaxf(v.y, 0.f) + fmaxf(v.z, 0.f) + fmaxf(v.w, 0.f);
            float m4 = fmaxf(fmaxf(v.x, v.y), fmaxf(v.z, v.w));
            unsigned any = __ballot_sync(FULL_MASK, m4 >= THRESH);   // warp-uniform
            if (any) {   // ~3% of batches: do per-component ballots
                float c[4] = {v.x, v.y, v.z, v.w};
#pragma unroll
                for (int q = 0; q < 4; q++) {
                    unsigned m = __ballot_sync(FULL_MASK, c[q] >= THRESH);
                    if (m) {
                        int slot = wcnt + __popc(m & ((1u << lane) - 1u));
                        if (c[q] >= THRESH) {
                            if (slot < WCAP) s_wkey[warp][slot] = f2k(c[q]);
                            else             ovf = true;
                        }
                        wcnt += __popc(m);
                    }
                }
            }
        }
    }
#pragma unroll
    for (int o = 16; o; o >>= 1) ms += __shfl_xor_sync(FULL_MASK, ms, o);
    ovf = __any_sync(FULL_MASK, ovf);
    if (lane == 0) { s_msum[warp] = ms; s_wcnt[warp] = ovf ? (WCAP + 1) : wcnt; }
    __syncthreads();

    // ============ Warp 0: mag total, prefix-scan of warp counts, fb decision ====
    if (warp == 0) {
        float m = (lane < NWARP) ? s_msum[lane] : 0.f;
#pragma unroll
        for (int o = 16; o; o >>= 1) m += __shfl_xor_sync(FULL_MASK, m, o);
        int c = (lane < NWARP) ? s_wcnt[lane] : 0;
        unsigned over = __ballot_sync(FULL_MASK, c > WCAP);
        int sc = c;
#pragma unroll
        for (int o = 1; o < 32; o <<= 1) {
            int t2 = __shfl_up_sync(FULL_MASK, sc, o);
            if (lane >= o) sc += t2;
        }
        int total = __shfl_sync(FULL_MASK, sc, NWARP - 1);
        if (lane < NWARP) s_off[lane] = sc - c;
        if (lane == 0) {
            s_mag = m;
            s_nc  = total;
            s_fb  = (over != 0 || total < KTOP) ? 1 : 0;
        }
    }
    __syncthreads();

    if (!s_fb) {
        // ======== compact per-warp segments into contiguous key array ===========
        {
            int base = s_off[warp], cnt = s_wcnt[warp];
            for (int i = lane; i < cnt; i += 32) s_key[base + i] = s_wkey[warp][i];
        }
        __syncthreads();
        const int nc = s_nc;

        // ======== O(nc^2) parallel rank select: find exact K-th key =============
        for (int m = tid; m < nc; m += TPB) {
            unsigned myk = s_key[m];
            int cg = 0, te = 0;
            for (int j = 0; j < nc; j++) {            // broadcast LDS, conflict-free
                unsigned k = s_key[j];
                cg += (k > myk);
                te += (k == myk);
            }
            if (cg < KTOP && cg + te >= KTOP) s_kth = myk;   // tie-group: same value
        }
        __syncthreads();
        const unsigned kth = s_kth;

        // ======== exact top-K sum (int64 fixed point => order-independent) ======
        long long acc = 0; int cgt = 0;
        for (int m = tid; m < nc; m += TPB) {
            unsigned k = s_key[m];
            if (k > kth) { acc += (long long)((double)k2f(k) * 4294967296.0); cgt++; }
        }
#pragma unroll
        for (int o = 16; o; o >>= 1) acc += __shfl_xor_sync(FULL_MASK, acc, o);
        cgt = __reduce_add_sync(FULL_MASK, cgt);
        if (lane == 0) { s_acc[warp] = acc; s_cnt[warp] = cgt; }
        __syncthreads();
        if (warp == 0) {
            long long a = (lane < NWARP) ? s_acc[lane] : 0;
            int      cc = (lane < NWARP) ? s_cnt[lane] : 0;
#pragma unroll
            for (int o = 16; o; o >>= 1) a += __shfl_xor_sync(FULL_MASK, a, o);
            cc = __reduce_add_sync(FULL_MASK, cc);
            if (lane == 0) {
                double magk = (double)a * (1.0 / 4294967296.0)
                            + (double)(KTOP - cc) * (double)k2f(kth);
                float r = (float)(magk / (double)s_mag);
                if (!isfinite(r)) r = 0.f;
                s_ratio = r;
            }
        }
        __syncthreads();
    } else {
        // ======== generic fallback: block bisection over gmem (unreachable stat.) =
        unsigned lo = 0u, hi = 0xFFFFFFFFu;
        while (hi - lo > 1u) {
            unsigned mid = lo + ((hi - lo) >> 1);
            int c = 0;
            for (int i = tid; i < N_COLS / 4; i += TPB) {
                float4 v = __ldcg(xr + i);
                c += (f2k(v.x) >= mid) + (f2k(v.y) >= mid) + (f2k(v.z) >= mid) + (f2k(v.w) >= mid);
            }
            c = __reduce_add_sync(FULL_MASK, c);
            if (lane == 0) s_cnt[warp] = c;
            __syncthreads();
            if (warp == 0) {
                int cc = (lane < NWARP) ? s_cnt[lane] : 0;
                cc = __reduce_add_sync(FULL_MASK, cc);
                if (lane == 0) s_tot = cc;
            }
            __syncthreads();
            if (s_tot >= KTOP) lo = mid; else hi = mid;
            __syncthreads();
        }
        double s = 0.0; int cg = 0;
        for (int i = tid; i < N_COLS / 4; i += TPB) {
            float4 v = __ldcg(xr + i);
            if (f2k(v.x) > lo) { s += v.x; cg++; }
            if (f2k(v.y) > lo) { s += v.y; cg++; }
            if (f2k(v.z) > lo) { s += v.z; cg++; }
            if (f2k(v.w) > lo) { s += v.w; cg++; }
        }
#pragma unroll
        for (int o = 16; o; o >>= 1) s += __shfl_xor_sync(FULL_MASK, s, o);
        cg = __reduce_add_sync(FULL_MASK, cg);
        if (lane == 0) { s_dsum[warp] = s; s_cnt[warp] = cg; }
        __syncthreads();
        if (warp == 0) {
            double ss = (lane < NWARP) ? s_dsum[lane] : 0.0;
#pragma unroll
            for (int o = 16; o; o >>= 1) ss += __shfl_xor_sync(FULL_MASK, ss, o);
            int cc = (lane < NWARP) ? s_cnt[lane] : 0;
            cc = __reduce_add_sync(FULL_MASK, cc);
            if (lane == 0) {
                double magk = ss + (double)(KTOP - cc) * (double)k2f(lo);
                float r = (float)(magk / (double)s_mag);
                if (!isfinite(r)) r = 0.f;
                s_ratio = r;
            }
        }
        __syncthreads();
    }

    // ============ Pass 2: L2 re-read, scale, streaming store =====================
    const float r = s_ratio;
#pragma unroll
    for (int ii = 0; ii < F4PT; ii += 8) {
        float4 t[8];
#pragma unroll
        for (int u = 0; u < 8; u++) t[u] = __ldcg(xr + (ii + u) * TPB + tid);
#pragma unroll
        for (int u = 0; u < 8; u++) {
            float4 v = t[u], o;
            o.x = fmaxf(v.x, 0.f) * r;
            o.y = fmaxf(v.y, 0.f) * r;
            o.z = fmaxf(v.z, 0.f) * r;
            o.w = fmaxf(v.w, 0.f) * r;
            __stcs(outr + (ii + u) * TPB + tid, o);
        }
    }
}

extern "C" void kernel_launch(void* const* d_in, const int* in_sizes, int n_in,
                              void* d_out, int out_size) {
    const float* x  = (const float*)d_in[0];
    float*      out = (float*)d_out;
    int n    = in_sizes[0];
    int rows = n / N_COLS;
    remaxkv_kernel<<<rows, TPB>>>(x, out);
}